// round 4
// baseline (speedup 1.0000x reference)
#include <cuda_runtime.h>
#include <math.h>

// Problem constants
#define BB   4
#define TT   1024
#define HIDN 1024
#define NH   8
#define DKK  128
#define DVV  128
#define CDIM 3072   // 2*H*DK + H*DV

// ---------------------------------------------------------------------------
// Scratch (device globals: no allocation allowed in kernel_launch)
// ---------------------------------------------------------------------------
__device__ float g_mixed[(size_t)BB * TT * CDIM];   // qkv projection, pre-conv
__device__ float g_qkvc [(size_t)BB * TT * CDIM];   // after causal depthwise conv
__device__ float g_z    [(size_t)BB * TT * HIDN];   // z projection
__device__ float g_opre [(size_t)BB * TT * NH * DVV]; // scan output (pre-norm)
__device__ float g_og   [(size_t)BB * TT * HIDN];   // gated/normed output (GEMM3 input)
__device__ float g_alpha[(size_t)BB * NH * TT];
__device__ float g_beta [(size_t)BB * NH * TT];

// ---------------------------------------------------------------------------
// GEMM (NT): C[M,N] = A[M,K] * B[N,K]^T, fp32, K = 1024 fixed.
// 128x128 tile, BK=16, 256 threads, 8x8 per-thread, register-prefetch pipeline.
// WHICH selects internal scratch pointers (host cannot take &__device__ array).
//   0: C = g_mixed (N=3072), A from param
//   1: C = g_z     (N=1024), A from param
//   2: A = g_og,   C from param (d_out)
// ---------------------------------------------------------------------------
template <int WHICH>
__global__ void __launch_bounds__(256, 2) gemm_nt(const float* __restrict__ Ain,
                                                  const float* __restrict__ Bw,
                                                  float* __restrict__ Cext,
                                                  int N) {
    const float* A = (WHICH == 2) ? g_og : Ain;
    float* C = (WHICH == 0) ? g_mixed : ((WHICH == 1) ? g_z : Cext);

    __shared__ float As[16][132];
    __shared__ float Bs[16][132];

    const int tid = threadIdx.x;
    const int bm = blockIdx.y * 128;
    const int bn = blockIdx.x * 128;
    const int tm = (tid >> 4) * 8;
    const int tn = (tid & 15) * 8;

    // load mapping: flat float4 index f covers the 128x16 tile (512 float4)
    const int m0  = tid >> 2;          // 0..63
    const int kq  = tid & 3;           // 0..3 (k-quad)
    const int m1  = m0 + 64;

    float acc[8][8];
#pragma unroll
    for (int i = 0; i < 8; i++)
#pragma unroll
        for (int j = 0; j < 8; j++) acc[i][j] = 0.f;

    const float* arow0 = A  + (size_t)(bm + m0) * 1024 + kq * 4;
    const float* arow1 = A  + (size_t)(bm + m1) * 1024 + kq * 4;
    const float* brow0 = Bw + (size_t)(bn + m0) * 1024 + kq * 4;
    const float* brow1 = Bw + (size_t)(bn + m1) * 1024 + kq * 4;

    float4 pa0 = *(const float4*)(arow0);
    float4 pa1 = *(const float4*)(arow1);
    float4 pb0 = *(const float4*)(brow0);
    float4 pb1 = *(const float4*)(brow1);

    for (int k0 = 0; k0 < 1024; k0 += 16) {
        __syncthreads();  // previous tile fully consumed
        As[kq*4+0][m0] = pa0.x; As[kq*4+1][m0] = pa0.y; As[kq*4+2][m0] = pa0.z; As[kq*4+3][m0] = pa0.w;
        As[kq*4+0][m1] = pa1.x; As[kq*4+1][m1] = pa1.y; As[kq*4+2][m1] = pa1.z; As[kq*4+3][m1] = pa1.w;
        Bs[kq*4+0][m0] = pb0.x; Bs[kq*4+1][m0] = pb0.y; Bs[kq*4+2][m0] = pb0.z; Bs[kq*4+3][m0] = pb0.w;
        Bs[kq*4+0][m1] = pb1.x; Bs[kq*4+1][m1] = pb1.y; Bs[kq*4+2][m1] = pb1.z; Bs[kq*4+3][m1] = pb1.w;
        __syncthreads();

        if (k0 + 16 < 1024) {   // prefetch next tile (latency overlapped with FFMAs)
            pa0 = *(const float4*)(arow0 + k0 + 16);
            pa1 = *(const float4*)(arow1 + k0 + 16);
            pb0 = *(const float4*)(brow0 + k0 + 16);
            pb1 = *(const float4*)(brow1 + k0 + 16);
        }

#pragma unroll
        for (int kk = 0; kk < 16; kk++) {
            float ar[8], br[8];
            *(float4*)&ar[0] = *(float4*)&As[kk][tm];
            *(float4*)&ar[4] = *(float4*)&As[kk][tm + 4];
            *(float4*)&br[0] = *(float4*)&Bs[kk][tn];
            *(float4*)&br[4] = *(float4*)&Bs[kk][tn + 4];
#pragma unroll
            for (int i = 0; i < 8; i++)
#pragma unroll
                for (int j = 0; j < 8; j++)
                    acc[i][j] = fmaf(ar[i], br[j], acc[i][j]);
        }
    }

#pragma unroll
    for (int i = 0; i < 8; i++) {
        float4 c0 = make_float4(acc[i][0], acc[i][1], acc[i][2], acc[i][3]);
        float4 c1 = make_float4(acc[i][4], acc[i][5], acc[i][6], acc[i][7]);
        float* crow = C + (size_t)(bm + tm + i) * N + bn + tn;
        *(float4*)(crow)     = c0;
        *(float4*)(crow + 4) = c1;
    }
}

// ---------------------------------------------------------------------------
// b/a projections + beta / alpha (per b,t,h scalars)
// grid = B*T blocks, 256 threads (warp per head)
// ---------------------------------------------------------------------------
__global__ void __launch_bounds__(256) smallproj_kernel(const float* __restrict__ hs,
                                                        const float* __restrict__ b_w,
                                                        const float* __restrict__ a_w,
                                                        const float* __restrict__ dt_bias,
                                                        const float* __restrict__ A_log) {
    __shared__ float sh[1024];
    const int bt  = blockIdx.x;
    const int tid = threadIdx.x;
    const float* row = hs + (size_t)bt * 1024;
    *(float4*)&sh[tid * 4] = *(const float4*)(row + tid * 4);
    __syncthreads();

    const int h = tid >> 5, lane = tid & 31;
    const float* bw = b_w + h * 1024;
    const float* aw = a_w + h * 1024;
    float sb = 0.f, sa = 0.f;
#pragma unroll
    for (int i = 0; i < 8; i++) {
        int idx = lane * 4 + i * 128;
        float4 x  = *(float4*)&sh[idx];
        float4 wb = *(const float4*)(bw + idx);
        float4 wa = *(const float4*)(aw + idx);
        sb += x.x * wb.x + x.y * wb.y + x.z * wb.z + x.w * wb.w;
        sa += x.x * wa.x + x.y * wa.y + x.z * wa.z + x.w * wa.w;
    }
#pragma unroll
    for (int m = 16; m; m >>= 1) {
        sb += __shfl_xor_sync(0xffffffffu, sb, m);
        sa += __shfl_xor_sync(0xffffffffu, sa, m);
    }
    if (lane == 0) {
        float beta = 1.f / (1.f + expf(-sb));
        float x  = sa + dt_bias[h];
        float sp = (x > 20.f) ? x : log1pf(expf(x));
        float g  = -expf(A_log[h]) * sp;
        int b = bt >> 10, t = bt & 1023;
        g_alpha[((b * NH + h) << 10) + t] = expf(g);
        g_beta [((b * NH + h) << 10) + t] = beta;
    }
}

// ---------------------------------------------------------------------------
// Causal depthwise conv1d (K=4): y[t] = w0*x[t-3] + w1*x[t-2] + w2*x[t-1] + w3*x[t]
// grid (C/256, T/128, B), 256 threads. Coalesced across channels.
// ---------------------------------------------------------------------------
__global__ void __launch_bounds__(256) conv_kernel(const float* __restrict__ conv_w) {
    const int c  = blockIdx.x * 256 + threadIdx.x;
    const int t0 = blockIdx.y * 128;
    const int b  = blockIdx.z;
    float4 w4 = *(const float4*)(conv_w + c * 4);
    const float* xin  = g_mixed + (size_t)b * TT * CDIM + c;
    float*       yout = g_qkvc  + (size_t)b * TT * CDIM + c;
    float x0 = (t0 >= 3) ? xin[(size_t)(t0 - 3) * CDIM] : 0.f;
    float x1 = (t0 >= 2) ? xin[(size_t)(t0 - 2) * CDIM] : 0.f;
    float x2 = (t0 >= 1) ? xin[(size_t)(t0 - 1) * CDIM] : 0.f;
#pragma unroll 4
    for (int t = t0; t < t0 + 128; t++) {
        float x3 = xin[(size_t)t * CDIM];
        yout[(size_t)t * CDIM] = w4.x * x0 + w4.y * x1 + w4.z * x2 + w4.w * x3;
        x0 = x1; x1 = x2; x2 = x3;
    }
}

// ---------------------------------------------------------------------------
// Gated delta-rule scan. dv columns are independent -> split dv across CTAs.
// grid = (4 dv-chunks, H, B) = 128 CTAs, 128 threads.
// Warp = 8 columns x 4 dk-splits (lane = col*4 + split). State S[32] in regs.
// Time-blocked (16 steps) smem staging of q/k/v/alpha/beta.
// ---------------------------------------------------------------------------
__global__ void __launch_bounds__(128) scan_kernel() {
    __shared__ float sk[16][128];
    __shared__ float sq[16][128];
    __shared__ float sv[16][32];
    __shared__ float so[16][32];
    __shared__ float sal[16];
    __shared__ float sbe[16];

    const int tid   = threadIdx.x;
    const int chunk = blockIdx.x;   // dv chunk (32 cols)
    const int h     = blockIdx.y;
    const int b     = blockIdx.z;

    const int lane = tid & 31;
    const int w    = tid >> 5;
    const int s    = lane & 3;              // dk split
    const int col  = w * 8 + (lane >> 2);   // 0..31 within chunk
    const int kb   = s * 32;                // dk base

    const float* qbase = g_qkvc + (size_t)b * TT * CDIM + h * 128;
    const float* abase = g_alpha + ((size_t)(b * NH + h) << 10);
    const float* bbase = g_beta  + ((size_t)(b * NH + h) << 10);

    float S[32];
#pragma unroll
    for (int j = 0; j < 32; j++) S[j] = 0.f;

    const int ltt  = tid >> 3;   // 0..15 (time row to load)
    const int lseg = tid & 7;    // 0..7  (16-float segment)

    for (int t0 = 0; t0 < TT; t0 += 16) {
        // ---- stage q/k/v/alpha/beta for 16 steps ----
        {
            const float* row = qbase + (size_t)(t0 + ltt) * CDIM;
#pragma unroll
            for (int u = 0; u < 4; u++) {
                int cc = lseg * 16 + u * 4;
                *(float4*)&sq[ltt][cc] = *(const float4*)(row + cc);          // q
                *(float4*)&sk[ltt][cc] = *(const float4*)(row + 1024 + cc);   // k
            }
            *(float4*)&sv[ltt][lseg * 4] =
                *(const float4*)(row + 2048 + chunk * 32 + lseg * 4);          // v (our chunk)
            if (tid < 16) {
                sal[tid] = abase[t0 + tid];
                sbe[tid] = bbase[t0 + tid];
            }
        }
        __syncthreads();

#pragma unroll 2
        for (int tt = 0; tt < 16; tt++) {
            const float alpha = sal[tt];
            float kr[32];
#pragma unroll
            for (int u = 0; u < 8; u++)
                *(float4*)&kr[u * 4] = *(float4*)&sk[tt][kb + u * 4];

            float kv0 = 0.f, kv1 = 0.f, kv2 = 0.f, kv3 = 0.f;
#pragma unroll
            for (int j = 0; j < 32; j += 4) {
                S[j]     *= alpha; kv0 = fmaf(kr[j],     S[j],     kv0);
                S[j + 1] *= alpha; kv1 = fmaf(kr[j + 1], S[j + 1], kv1);
                S[j + 2] *= alpha; kv2 = fmaf(kr[j + 2], S[j + 2], kv2);
                S[j + 3] *= alpha; kv3 = fmaf(kr[j + 3], S[j + 3], kv3);
            }
            float kv = (kv0 + kv1) + (kv2 + kv3);
            kv += __shfl_xor_sync(0xffffffffu, kv, 1);
            kv += __shfl_xor_sync(0xffffffffu, kv, 2);

            const float wv = (sv[tt][col] - kv) * sbe[tt];

            float qr[32];
#pragma unroll
            for (int u = 0; u < 8; u++)
                *(float4*)&qr[u * 4] = *(float4*)&sq[tt][kb + u * 4];

            float o0 = 0.f, o1 = 0.f, o2 = 0.f, o3 = 0.f;
#pragma unroll
            for (int j = 0; j < 32; j += 4) {
                S[j]     = fmaf(kr[j],     wv, S[j]);     o0 = fmaf(qr[j],     S[j],     o0);
                S[j + 1] = fmaf(kr[j + 1], wv, S[j + 1]); o1 = fmaf(qr[j + 1], S[j + 1], o1);
                S[j + 2] = fmaf(kr[j + 2], wv, S[j + 2]); o2 = fmaf(qr[j + 2], S[j + 2], o2);
                S[j + 3] = fmaf(kr[j + 3], wv, S[j + 3]); o3 = fmaf(qr[j + 3], S[j + 3], o3);
            }
            float o = (o0 + o1) + (o2 + o3);
            o += __shfl_xor_sync(0xffffffffu, o, 1);
            o += __shfl_xor_sync(0xffffffffu, o, 2);
            if (s == 0) so[tt][col] = o;
        }
        __syncthreads();

        // ---- flush outputs (coalesced) ----
        for (int idx = tid; idx < 512; idx += 128) {
            int tt = idx >> 5, dd = idx & 31;
            g_opre[(((size_t)(b * TT + t0 + tt)) * NH + h) * 128 + chunk * 32 + dd] = so[tt][dd];
        }
        // safe: next compute's `so` writes happen only after the next __syncthreads()
    }
}

// ---------------------------------------------------------------------------
// Gated RMSNorm: y = o * rsqrt(mean(o^2)+eps) * norm_w * silu(z)
// grid = B*T blocks, 256 threads (warp per head).
// ---------------------------------------------------------------------------
__global__ void __launch_bounds__(256) normgate_kernel(const float* __restrict__ norm_w) {
    const int bt   = blockIdx.x;
    const int h    = threadIdx.x >> 5;
    const int lane = threadIdx.x & 31;

    const size_t obase = ((size_t)bt * NH + h) * 128 + lane * 4;
    float4 o4 = *(const float4*)(g_opre + obase);
    float ss = o4.x * o4.x + o4.y * o4.y + o4.z * o4.z + o4.w * o4.w;
#pragma unroll
    for (int m = 16; m; m >>= 1) ss += __shfl_xor_sync(0xffffffffu, ss, m);
    const float scale = rsqrtf(ss * (1.f / 128.f) + 1e-6f);

    const size_t zbase = (size_t)bt * 1024 + h * 128 + lane * 4;
    float4 z4 = *(const float4*)(g_z + zbase);
    float4 nw = *(const float4*)(norm_w + lane * 4);
    float4 r;
    r.x = o4.x * scale * nw.x * (z4.x / (1.f + expf(-z4.x)));
    r.y = o4.y * scale * nw.y * (z4.y / (1.f + expf(-z4.y)));
    r.z = o4.z * scale * nw.z * (z4.z / (1.f + expf(-z4.z)));
    r.w = o4.w * scale * nw.w * (z4.w / (1.f + expf(-z4.w)));
    *(float4*)(g_og + zbase) = r;
}

// ---------------------------------------------------------------------------
// kernel_launch: graph-capturable, allocation-free, deterministic.
// ---------------------------------------------------------------------------
extern "C" void kernel_launch(void* const* d_in, const int* in_sizes, int n_in,
                              void* d_out, int out_size) {
    const float* hs      = (const float*)d_in[0];
    const float* qkv_w   = (const float*)d_in[1];
    const float* z_w     = (const float*)d_in[2];
    const float* b_w     = (const float*)d_in[3];
    const float* a_w     = (const float*)d_in[4];
    const float* conv_w  = (const float*)d_in[5];
    const float* dt_bias = (const float*)d_in[6];
    const float* A_log   = (const float*)d_in[7];
    const float* norm_w  = (const float*)d_in[8];
    const float* out_w   = (const float*)d_in[9];
    float* out = (float*)d_out;

    // alpha/beta (independent of the big GEMMs)
    smallproj_kernel<<<BB * TT, 256>>>(hs, b_w, a_w, dt_bias, A_log);

    // qkv projection -> g_mixed
    gemm_nt<0><<<dim3(CDIM / 128, (BB * TT) / 128), 256>>>(hs, qkv_w, nullptr, CDIM);

    // causal depthwise conv -> g_qkvc
    conv_kernel<<<dim3(CDIM / 256, TT / 128, BB), 256>>>(conv_w);

    // z projection -> g_z
    gemm_nt<1><<<dim3(HIDN / 128, (BB * TT) / 128), 256>>>(hs, z_w, nullptr, HIDN);

    // gated delta-rule recurrence -> g_opre
    scan_kernel<<<dim3(4, NH, BB), 128>>>();

    // gated RMSNorm -> g_og
    normgate_kernel<<<BB * TT, 256>>>(norm_w);

    // output projection -> d_out
    gemm_nt<2><<<dim3(HIDN / 128, (BB * TT) / 128), 256>>>(nullptr, out_w, out, HIDN);
}

// round 5
// speedup vs baseline: 1.0511x; 1.0511x over previous
#include <cuda_runtime.h>
#include <math.h>

// Problem constants
#define BB   4
#define TT   1024
#define HIDN 1024
#define NH   8
#define DKK  128
#define DVV  128
#define CDIM 3072   // 2*H*DK + H*DV

typedef unsigned long long u64;

// ---------------------------------------------------------------------------
// f32x2 packed helpers (Blackwell sm_103a: FFMA2 only reachable via PTX)
// ---------------------------------------------------------------------------
__device__ __forceinline__ void fma2(u64& d, u64 a, u64 b) {
    asm("fma.rn.f32x2 %0, %1, %2, %0;" : "+l"(d) : "l"(a), "l"(b));
}
__device__ __forceinline__ void mul2i(u64& d, u64 a) {
    asm("mul.rn.f32x2 %0, %0, %1;" : "+l"(d) : "l"(a));
}
__device__ __forceinline__ u64 add2(u64 a, u64 b) {
    u64 r; asm("add.rn.f32x2 %0, %1, %2;" : "=l"(r) : "l"(a), "l"(b)); return r;
}
__device__ __forceinline__ u64 pack_dup(float v) {
    u64 r; asm("mov.b64 %0, {%1, %1};" : "=l"(r) : "f"(v)); return r;
}
__device__ __forceinline__ float2 unpk(u64 v) {
    float2 r; asm("mov.b64 {%0, %1}, %2;" : "=f"(r.x), "=f"(r.y) : "l"(v)); return r;
}

// ---------------------------------------------------------------------------
// Scratch (device globals: no allocation allowed in kernel_launch)
// ---------------------------------------------------------------------------
__device__ float g_mixed[(size_t)BB * TT * CDIM];   // qkv projection, pre-conv
__device__ float g_qkvc [(size_t)BB * TT * CDIM];   // after causal depthwise conv
__device__ float g_z    [(size_t)BB * TT * HIDN];   // z projection
__device__ float g_opre [(size_t)BB * TT * NH * DVV]; // scan output (pre-norm)
__device__ float g_og   [(size_t)BB * TT * HIDN];   // gated/normed output
__device__ float g_alpha[(size_t)BB * NH * TT];
__device__ float g_beta [(size_t)BB * NH * TT];

// ---------------------------------------------------------------------------
// GEMM (NT): C[M,N] = A[M,K] * B[N,K]^T, fp32, K = 1024 fixed.
// 128x128 tile, BK=16, 256 threads, 8x8 per-thread via FFMA2 (f32x2 pairs).
// A staged DUPLICATED in smem so ld.shared.b64 yields (a,a) pairs directly.
//   WHICH 0: C = g_mixed; 1: C = g_z; 2: A = g_og, C = param
// ---------------------------------------------------------------------------
template <int WHICH>
__global__ void __launch_bounds__(256, 2) gemm_nt(const float* __restrict__ Ain,
                                                  const float* __restrict__ Bw,
                                                  float* __restrict__ Cext,
                                                  int N) {
    const float* A = (WHICH == 2) ? g_og : Ain;
    float* C = (WHICH == 0) ? g_mixed : ((WHICH == 1) ? g_z : Cext);

    __shared__ float As[16][264];   // duplicated pairs: 256 data + 8 pad
    __shared__ float Bs[16][132];

    const int tid = threadIdx.x;
    const int bm = blockIdx.y * 128;
    const int bn = blockIdx.x * 128;
    const int tm = (tid >> 4) * 8;
    const int tn = (tid & 15) * 8;

    const int m0  = tid >> 2;          // 0..63
    const int kq  = tid & 3;           // 0..3 (k-quad)
    const int m1  = m0 + 64;

    u64 acc[8][4];
#pragma unroll
    for (int i = 0; i < 8; i++)
#pragma unroll
        for (int j = 0; j < 4; j++) acc[i][j] = 0ull;

    const float* arow0 = A  + (size_t)(bm + m0) * 1024 + kq * 4;
    const float* arow1 = A  + (size_t)(bm + m1) * 1024 + kq * 4;
    const float* brow0 = Bw + (size_t)(bn + m0) * 1024 + kq * 4;
    const float* brow1 = Bw + (size_t)(bn + m1) * 1024 + kq * 4;

    float4 pa0 = *(const float4*)(arow0);
    float4 pa1 = *(const float4*)(arow1);
    float4 pb0 = *(const float4*)(brow0);
    float4 pb1 = *(const float4*)(brow1);

    for (int k0 = 0; k0 < 1024; k0 += 16) {
        __syncthreads();  // previous tile fully consumed
        // A duplicated (pair) stores
        *(float2*)&As[kq*4+0][2*m0] = make_float2(pa0.x, pa0.x);
        *(float2*)&As[kq*4+1][2*m0] = make_float2(pa0.y, pa0.y);
        *(float2*)&As[kq*4+2][2*m0] = make_float2(pa0.z, pa0.z);
        *(float2*)&As[kq*4+3][2*m0] = make_float2(pa0.w, pa0.w);
        *(float2*)&As[kq*4+0][2*m1] = make_float2(pa1.x, pa1.x);
        *(float2*)&As[kq*4+1][2*m1] = make_float2(pa1.y, pa1.y);
        *(float2*)&As[kq*4+2][2*m1] = make_float2(pa1.z, pa1.z);
        *(float2*)&As[kq*4+3][2*m1] = make_float2(pa1.w, pa1.w);
        Bs[kq*4+0][m0] = pb0.x; Bs[kq*4+1][m0] = pb0.y; Bs[kq*4+2][m0] = pb0.z; Bs[kq*4+3][m0] = pb0.w;
        Bs[kq*4+0][m1] = pb1.x; Bs[kq*4+1][m1] = pb1.y; Bs[kq*4+2][m1] = pb1.z; Bs[kq*4+3][m1] = pb1.w;
        __syncthreads();

        if (k0 + 16 < 1024) {   // prefetch next tile into registers
            pa0 = *(const float4*)(arow0 + k0 + 16);
            pa1 = *(const float4*)(arow1 + k0 + 16);
            pb0 = *(const float4*)(brow0 + k0 + 16);
            pb1 = *(const float4*)(brow1 + k0 + 16);
        }

#pragma unroll
        for (int kk = 0; kk < 16; kk++) {
            const ulonglong2* ap = (const ulonglong2*)&As[kk][2 * tm];
            const ulonglong2* bp = (const ulonglong2*)&Bs[kk][tn];
            ulonglong2 a01 = ap[0], a23 = ap[1], a45 = ap[2], a67 = ap[3];
            ulonglong2 b01 = bp[0], b23 = bp[1];
            u64 ar[8] = {a01.x, a01.y, a23.x, a23.y, a45.x, a45.y, a67.x, a67.y};
            u64 br[4] = {b01.x, b01.y, b23.x, b23.y};
#pragma unroll
            for (int i = 0; i < 8; i++) {
                fma2(acc[i][0], ar[i], br[0]);
                fma2(acc[i][1], ar[i], br[1]);
                fma2(acc[i][2], ar[i], br[2]);
                fma2(acc[i][3], ar[i], br[3]);
            }
        }
    }

#pragma unroll
    for (int i = 0; i < 8; i++) {
        float* crow = C + (size_t)(bm + tm + i) * N + bn + tn;
        *(ulonglong2*)(crow)     = make_ulonglong2(acc[i][0], acc[i][1]);
        *(ulonglong2*)(crow + 4) = make_ulonglong2(acc[i][2], acc[i][3]);
    }
}

// ---------------------------------------------------------------------------
// b/a projections + beta / alpha (per b,t,h scalars)
// ---------------------------------------------------------------------------
__global__ void __launch_bounds__(256) smallproj_kernel(const float* __restrict__ hs,
                                                        const float* __restrict__ b_w,
                                                        const float* __restrict__ a_w,
                                                        const float* __restrict__ dt_bias,
                                                        const float* __restrict__ A_log) {
    __shared__ float sh[1024];
    const int bt  = blockIdx.x;
    const int tid = threadIdx.x;
    const float* row = hs + (size_t)bt * 1024;
    *(float4*)&sh[tid * 4] = *(const float4*)(row + tid * 4);
    __syncthreads();

    const int h = tid >> 5, lane = tid & 31;
    const float* bw = b_w + h * 1024;
    const float* aw = a_w + h * 1024;
    float sb = 0.f, sa = 0.f;
#pragma unroll
    for (int i = 0; i < 8; i++) {
        int idx = lane * 4 + i * 128;
        float4 x  = *(float4*)&sh[idx];
        float4 wb = *(const float4*)(bw + idx);
        float4 wa = *(const float4*)(aw + idx);
        sb += x.x * wb.x + x.y * wb.y + x.z * wb.z + x.w * wb.w;
        sa += x.x * wa.x + x.y * wa.y + x.z * wa.z + x.w * wa.w;
    }
#pragma unroll
    for (int m = 16; m; m >>= 1) {
        sb += __shfl_xor_sync(0xffffffffu, sb, m);
        sa += __shfl_xor_sync(0xffffffffu, sa, m);
    }
    if (lane == 0) {
        float beta = 1.f / (1.f + expf(-sb));
        float x  = sa + dt_bias[h];
        float sp = (x > 20.f) ? x : log1pf(expf(x));
        float g  = -expf(A_log[h]) * sp;
        int b = bt >> 10, t = bt & 1023;
        g_alpha[((b * NH + h) << 10) + t] = expf(g);
        g_beta [((b * NH + h) << 10) + t] = beta;
    }
}

// ---------------------------------------------------------------------------
// Causal depthwise conv1d (K=4)
// ---------------------------------------------------------------------------
__global__ void __launch_bounds__(256) conv_kernel(const float* __restrict__ conv_w) {
    const int c  = blockIdx.x * 256 + threadIdx.x;
    const int t0 = blockIdx.y * 128;
    const int b  = blockIdx.z;
    float4 w4 = *(const float4*)(conv_w + c * 4);
    const float* xin  = g_mixed + (size_t)b * TT * CDIM + c;
    float*       yout = g_qkvc  + (size_t)b * TT * CDIM + c;
    float x0 = (t0 >= 3) ? xin[(size_t)(t0 - 3) * CDIM] : 0.f;
    float x1 = (t0 >= 2) ? xin[(size_t)(t0 - 2) * CDIM] : 0.f;
    float x2 = (t0 >= 1) ? xin[(size_t)(t0 - 1) * CDIM] : 0.f;
#pragma unroll 4
    for (int t = t0; t < t0 + 128; t++) {
        float x3 = xin[(size_t)t * CDIM];
        yout[(size_t)t * CDIM] = w4.x * x0 + w4.y * x1 + w4.z * x2 + w4.w * x3;
        x0 = x1; x1 = x2; x2 = x3;
    }
}

// ---------------------------------------------------------------------------
// Gated delta-rule scan v2.
// grid = (4 dv-chunks of 32 cols, H, B) = 128 CTAs, 256 threads (2 warps/SMSP).
// Warp = 4 cols x 8 dk-splits (lane = colw*8 + split), S = 16 dk floats/thread
// held as 8 f32x2 pairs. k/q staged in smem with stride-20 padded groups so the
// 8 splits' 16B loads hit disjoint bank groups. Register prefetch of the next
// 16-step block overlaps LDG latency with compute.
// ---------------------------------------------------------------------------
__global__ void __launch_bounds__(256) scan_kernel() {
    __shared__ float sk[16][160];   // 8 groups * (16 data + 4 pad)
    __shared__ float sq[16][160];
    __shared__ float sv[16][32];
    __shared__ float so[16][32];
    __shared__ float sal[16];
    __shared__ float sbe[16];

    const int tid   = threadIdx.x;
    const int chunk = blockIdx.x;   // dv chunk (32 cols)
    const int h     = blockIdx.y;
    const int b     = blockIdx.z;

    const int lane  = tid & 31;
    const int w     = tid >> 5;             // warp 0..7
    const int split = lane & 7;             // dk split (16 dk each)
    const int col   = w * 4 + (lane >> 3);  // 0..31 within chunk
    const int kbp   = split * 20;           // padded smem base for this split

    const float* qbase = g_qkvc + (size_t)b * TT * CDIM + h * 128;
    const float* abase = g_alpha + ((size_t)(b * NH + h) << 10);
    const float* bbase = g_beta  + ((size_t)(b * NH + h) << 10);

    u64 S2[8];
#pragma unroll
    for (int j = 0; j < 8; j++) S2[j] = 0ull;

    // staging mapping
    const int ltt  = tid >> 4;     // 0..15 time row
    const int lseg = tid & 15;     // 0..15
    const int cc0  = lseg * 8;
    const int cc1  = cc0 + 4;
    const int d0   = cc0 + ((cc0 >> 4) << 2);   // padded dst
    const int d1   = cc1 + ((cc1 >> 4) << 2);

    float4 pq0, pq1, pk0, pk1, pv;
    float pal = 0.f, pbe = 0.f;

    // prefetch block 0
    {
        const float* row = qbase + (size_t)ltt * CDIM;
        pq0 = *(const float4*)(row + cc0);
        pq1 = *(const float4*)(row + cc1);
        pk0 = *(const float4*)(row + 1024 + cc0);
        pk1 = *(const float4*)(row + 1024 + cc1);
        if (lseg < 8) pv = *(const float4*)(row + 2048 + chunk * 32 + lseg * 4);
        if (tid < 16) { pal = abase[tid]; pbe = bbase[tid]; }
    }

    for (int t0 = 0; t0 < TT; t0 += 16) {
        __syncthreads();   // prior compute done (trivial at t0=0)
        if (t0 > 0) {      // flush previous block's outputs
            for (int idx = tid; idx < 512; idx += 256) {
                int tt = idx >> 5, dd = idx & 31;
                g_opre[(((size_t)(b * TT + (t0 - 16) + tt)) * NH + h) * 128 + chunk * 32 + dd] = so[tt][dd];
            }
        }
        // store staged registers
        *(float4*)&sq[ltt][d0] = pq0;
        *(float4*)&sq[ltt][d1] = pq1;
        *(float4*)&sk[ltt][d0] = pk0;
        *(float4*)&sk[ltt][d1] = pk1;
        if (lseg < 8) *(float4*)&sv[ltt][lseg * 4] = pv;
        if (tid < 16) { sal[tid] = pal; sbe[tid] = pbe; }
        __syncthreads();

        if (t0 + 16 < TT) {   // prefetch next block (overlaps compute)
            const float* row = qbase + (size_t)(t0 + 16 + ltt) * CDIM;
            pq0 = *(const float4*)(row + cc0);
            pq1 = *(const float4*)(row + cc1);
            pk0 = *(const float4*)(row + 1024 + cc0);
            pk1 = *(const float4*)(row + 1024 + cc1);
            if (lseg < 8) pv = *(const float4*)(row + 2048 + chunk * 32 + lseg * 4);
            if (tid < 16) { pal = abase[t0 + 16 + tid]; pbe = bbase[t0 + 16 + tid]; }
        }

#pragma unroll 2
        for (int tt = 0; tt < 16; tt++) {
            const float alpha = sal[tt];
            const float beta  = sbe[tt];
            const u64 alpha2 = pack_dup(alpha);

            const ulonglong2* kp = (const ulonglong2*)&sk[tt][kbp];
            ulonglong2 k01 = kp[0], k23 = kp[1], k45 = kp[2], k67 = kp[3];
            u64 kr[8] = {k01.x, k01.y, k23.x, k23.y, k45.x, k45.y, k67.x, k67.y};

            u64 kva = 0ull, kvb = 0ull;
#pragma unroll
            for (int j = 0; j < 8; j += 2) {
                mul2i(S2[j],     alpha2); fma2(kva, kr[j],     S2[j]);
                mul2i(S2[j + 1], alpha2); fma2(kvb, kr[j + 1], S2[j + 1]);
            }
            float2 kc = unpk(add2(kva, kvb));
            float kv = kc.x + kc.y;
            kv += __shfl_xor_sync(0xffffffffu, kv, 1);
            kv += __shfl_xor_sync(0xffffffffu, kv, 2);
            kv += __shfl_xor_sync(0xffffffffu, kv, 4);

            const float wv = (sv[tt][col] - kv) * beta;
            const u64 wv2 = pack_dup(wv);

            const ulonglong2* qp = (const ulonglong2*)&sq[tt][kbp];
            ulonglong2 q01 = qp[0], q23 = qp[1], q45 = qp[2], q67 = qp[3];
            u64 qr[8] = {q01.x, q01.y, q23.x, q23.y, q45.x, q45.y, q67.x, q67.y};

            u64 oa = 0ull, ob = 0ull;
#pragma unroll
            for (int j = 0; j < 8; j += 2) {
                fma2(S2[j],     kr[j],     wv2); fma2(oa, qr[j],     S2[j]);
                fma2(S2[j + 1], kr[j + 1], wv2); fma2(ob, qr[j + 1], S2[j + 1]);
            }
            float2 oc = unpk(add2(oa, ob));
            float o = oc.x + oc.y;
            o += __shfl_xor_sync(0xffffffffu, o, 1);
            o += __shfl_xor_sync(0xffffffffu, o, 2);
            o += __shfl_xor_sync(0xffffffffu, o, 4);
            if (split == 0) so[tt][col] = o;
        }
    }

    __syncthreads();
    for (int idx = tid; idx < 512; idx += 256) {
        int tt = idx >> 5, dd = idx & 31;
        g_opre[(((size_t)(b * TT + (TT - 16) + tt)) * NH + h) * 128 + chunk * 32 + dd] = so[tt][dd];
    }
}

// ---------------------------------------------------------------------------
// Gated RMSNorm: y = o * rsqrt(mean(o^2)+eps) * norm_w * silu(z)
// ---------------------------------------------------------------------------
__global__ void __launch_bounds__(256) normgate_kernel(const float* __restrict__ norm_w) {
    const int bt   = blockIdx.x;
    const int h    = threadIdx.x >> 5;
    const int lane = threadIdx.x & 31;

    const size_t obase = ((size_t)bt * NH + h) * 128 + lane * 4;
    float4 o4 = *(const float4*)(g_opre + obase);
    float ss = o4.x * o4.x + o4.y * o4.y + o4.z * o4.z + o4.w * o4.w;
#pragma unroll
    for (int m = 16; m; m >>= 1) ss += __shfl_xor_sync(0xffffffffu, ss, m);
    const float scale = rsqrtf(ss * (1.f / 128.f) + 1e-6f);

    const size_t zbase = (size_t)bt * 1024 + h * 128 + lane * 4;
    float4 z4 = *(const float4*)(g_z + zbase);
    float4 nw = *(const float4*)(norm_w + lane * 4);
    float4 r;
    r.x = o4.x * scale * nw.x * (z4.x / (1.f + expf(-z4.x)));
    r.y = o4.y * scale * nw.y * (z4.y / (1.f + expf(-z4.y)));
    r.z = o4.z * scale * nw.z * (z4.z / (1.f + expf(-z4.z)));
    r.w = o4.w * scale * nw.w * (z4.w / (1.f + expf(-z4.w)));
    *(float4*)(g_og + zbase) = r;
}

// ---------------------------------------------------------------------------
// kernel_launch
// ---------------------------------------------------------------------------
extern "C" void kernel_launch(void* const* d_in, const int* in_sizes, int n_in,
                              void* d_out, int out_size) {
    const float* hs      = (const float*)d_in[0];
    const float* qkv_w   = (const float*)d_in[1];
    const float* z_w     = (const float*)d_in[2];
    const float* b_w     = (const float*)d_in[3];
    const float* a_w     = (const float*)d_in[4];
    const float* conv_w  = (const float*)d_in[5];
    const float* dt_bias = (const float*)d_in[6];
    const float* A_log   = (const float*)d_in[7];
    const float* norm_w  = (const float*)d_in[8];
    const float* out_w   = (const float*)d_in[9];
    float* out = (float*)d_out;

    smallproj_kernel<<<BB * TT, 256>>>(hs, b_w, a_w, dt_bias, A_log);
    gemm_nt<0><<<dim3(CDIM / 128, (BB * TT) / 128), 256>>>(hs, qkv_w, nullptr, CDIM);
    conv_kernel<<<dim3(CDIM / 256, TT / 128, BB), 256>>>(conv_w);
    gemm_nt<1><<<dim3(HIDN / 128, (BB * TT) / 128), 256>>>(hs, z_w, nullptr, HIDN);
    scan_kernel<<<dim3(4, NH, BB), 256>>>();
    normgate_kernel<<<BB * TT, 256>>>(norm_w);
    gemm_nt<2><<<dim3(HIDN / 128, (BB * TT) / 128), 256>>>(nullptr, out_w, out, HIDN);
}

// round 7
// speedup vs baseline: 1.9840x; 1.8875x over previous
#include <cuda_runtime.h>
#include <cuda_bf16.h>
#include <math.h>
#include <stdint.h>

// Problem constants
#define BB   4
#define TT   1024
#define HIDN 1024
#define NH   8
#define CDIM 3072   // 2*H*DK + H*DV
#define K3   3072   // tripled K for split-bf16 GEMM

// ---------------------------------------------------------------------------
// Scratch (device globals; allocation is forbidden)
// ---------------------------------------------------------------------------
__device__ float g_mixed[(size_t)BB * TT * CDIM];
__device__ float g_qkvc [(size_t)BB * TT * CDIM];
__device__ float g_z    [(size_t)BB * TT * HIDN];
__device__ float g_opre [(size_t)BB * TT * HIDN];
__device__ float g_alpha[(size_t)BB * NH * TT];
__device__ float g_beta [(size_t)BB * NH * TT];

// split-bf16 operands (K-tripled): A = [hi, lo, hi], B = [hi, hi, lo]
__device__ __nv_bfloat16 g_A3hs [(size_t)BB * TT * K3];
__device__ __nv_bfloat16 g_A3og [(size_t)BB * TT * K3];
__device__ __nv_bfloat16 g_B3qkv[(size_t)CDIM * K3];
__device__ __nv_bfloat16 g_B3z  [(size_t)HIDN * K3];
__device__ __nv_bfloat16 g_B3out[(size_t)HIDN * K3];

// ---------------------------------------------------------------------------
// Base-ISA tensor helpers (sm_80+: mma.sync / ldmatrix / cp.async).
// NOTE: harness PTX targets compute_103 (no 'a') -> tcgen05 is unavailable.
// ---------------------------------------------------------------------------
__device__ __forceinline__ uint32_t smem_u32(const void* p) {
    return (uint32_t)__cvta_generic_to_shared(p);
}
__device__ __forceinline__ void cp_async16(uint32_t dst, const void* src) {
    asm volatile("cp.async.cg.shared.global [%0], [%1], 16;" :: "r"(dst), "l"(src) : "memory");
}
#define CP_COMMIT() asm volatile("cp.async.commit_group;" ::: "memory")
#define CP_WAIT1()  asm volatile("cp.async.wait_group 1;" ::: "memory")

__device__ __forceinline__ void ldsm_x4(uint32_t* r, uint32_t addr) {
    asm volatile("ldmatrix.sync.aligned.m8n8.x4.shared.b16 {%0,%1,%2,%3}, [%4];"
                 : "=r"(r[0]), "=r"(r[1]), "=r"(r[2]), "=r"(r[3]) : "r"(addr));
}
__device__ __forceinline__ void ldsm_x2(uint32_t* r, uint32_t addr) {
    asm volatile("ldmatrix.sync.aligned.m8n8.x2.shared.b16 {%0,%1}, [%2];"
                 : "=r"(r[0]), "=r"(r[1]) : "r"(addr));
}
__device__ __forceinline__ void mma16816(float* c, const uint32_t* a, const uint32_t* b) {
    asm volatile("mma.sync.aligned.m16n8k16.row.col.f32.bf16.bf16.f32 "
                 "{%0,%1,%2,%3}, {%4,%5,%6,%7}, {%8,%9}, {%0,%1,%2,%3};"
                 : "+f"(c[0]), "+f"(c[1]), "+f"(c[2]), "+f"(c[3])
                 : "r"(a[0]), "r"(a[1]), "r"(a[2]), "r"(a[3]), "r"(b[0]), "r"(b[1]));
}

// hi/lo split helpers
__device__ __forceinline__ void split_bf16(float x, __nv_bfloat16& h, __nv_bfloat16& l) {
    h = __float2bfloat16_rn(x);
    l = __float2bfloat16_rn(x - __bfloat162float(h));
}
__device__ __forceinline__ void st_bf16x4(__nv_bfloat16* p, __nv_bfloat16 a, __nv_bfloat16 b,
                                          __nv_bfloat16 c, __nv_bfloat16 d) {
    __nv_bfloat162 v0; v0.x = a; v0.y = b;
    __nv_bfloat162 v1; v1.x = c; v1.y = d;
    *(__nv_bfloat162*)(p)     = v0;
    *(__nv_bfloat162*)(p + 2) = v1;
}

// ---------------------------------------------------------------------------
// Operand conversion: fp32 -> K-tripled split-bf16
// ---------------------------------------------------------------------------
__global__ void __launch_bounds__(256) convert_hs_kernel(const float* __restrict__ hs) {
    const int row = blockIdx.x;
    const int c   = threadIdx.x * 4;
    float4 x = *(const float4*)(hs + (size_t)row * 1024 + c);
    __nv_bfloat16 h0, h1, h2, h3, l0, l1, l2, l3;
    split_bf16(x.x, h0, l0); split_bf16(x.y, h1, l1);
    split_bf16(x.z, h2, l2); split_bf16(x.w, h3, l3);
    __nv_bfloat16* dst = g_A3hs + (size_t)row * K3 + c;
    st_bf16x4(dst,        h0, h1, h2, h3);
    st_bf16x4(dst + 1024, l0, l1, l2, l3);
    st_bf16x4(dst + 2048, h0, h1, h2, h3);
}

template <int W>
__global__ void __launch_bounds__(256) convert_w_kernel(const float* __restrict__ src) {
    __nv_bfloat16* out = (W == 0) ? g_B3qkv : ((W == 1) ? g_B3z : g_B3out);
    const int row = blockIdx.x;
    const int c   = threadIdx.x * 4;
    float4 x = *(const float4*)(src + (size_t)row * 1024 + c);
    __nv_bfloat16 h0, h1, h2, h3, l0, l1, l2, l3;
    split_bf16(x.x, h0, l0); split_bf16(x.y, h1, l1);
    split_bf16(x.z, h2, l2); split_bf16(x.w, h3, l3);
    __nv_bfloat16* dst = out + (size_t)row * K3 + c;
    st_bf16x4(dst,        h0, h1, h2, h3);
    st_bf16x4(dst + 1024, h0, h1, h2, h3);
    st_bf16x4(dst + 2048, l0, l1, l2, l3);
}

// ---------------------------------------------------------------------------
// HMMA GEMM (NT): C[M,N] = A'[M,K3] * B'[N,K3]^T, bf16 in / fp32 out.
// 128x128 tile, BK=32, 256 threads (8 warps, 2x4), warp tile 64x32.
// cp.async double-buffered smem; ldmatrix fragments; mma.sync m16n8k16.
//   WHICH 0: A3hs x B3qkv -> g_mixed (N=3072)
//   WHICH 1: A3hs x B3z   -> g_z     (N=1024)
//   WHICH 2: A3og x B3out -> Cext    (N=1024)
// ---------------------------------------------------------------------------
template <int WHICH>
__global__ void __launch_bounds__(256) gemm_mma(float* __restrict__ Cext, int N) {
    const __nv_bfloat16* A = (WHICH == 2) ? g_A3og : g_A3hs;
    const __nv_bfloat16* B = (WHICH == 0) ? g_B3qkv : ((WHICH == 1) ? g_B3z : g_B3out);
    float* C = (WHICH == 0) ? g_mixed : ((WHICH == 1) ? g_z : Cext);

    // padded stride 40 bf16 (80B): 16B groups land on disjoint bank sets
    __shared__ __nv_bfloat16 As[2][128][40];
    __shared__ __nv_bfloat16 Bs[2][128][40];

    const int tid  = threadIdx.x;
    const int bn   = blockIdx.x * 128;
    const int bm   = blockIdx.y * 128;
    const int warp = tid >> 5, lane = tid & 31;
    const int wm   = (warp >> 2) * 64;   // 0 or 64
    const int wn   = (warp & 3) * 32;    // 0..96

    float acc[4][4][4];
#pragma unroll
    for (int im = 0; im < 4; im++)
#pragma unroll
        for (int in = 0; in < 4; in++)
#pragma unroll
            for (int r = 0; r < 4; r++) acc[im][in][r] = 0.f;

    // loader mapping: 512 16B chunks per operand; thread -> chunks tid, tid+256
    const int lr = tid >> 2;        // 0..63
    const int kc = tid & 3;         // 0..3 (16B unit within 64B row)
    const __nv_bfloat16* Ag0 = A + (size_t)(bm + lr)      * K3 + kc * 8;
    const __nv_bfloat16* Ag1 = A + (size_t)(bm + lr + 64) * K3 + kc * 8;
    const __nv_bfloat16* Bg0 = B + (size_t)(bn + lr)      * K3 + kc * 8;
    const __nv_bfloat16* Bg1 = B + (size_t)(bn + lr + 64) * K3 + kc * 8;

    const uint32_t aS = smem_u32(&As[0][0][0]);
    const uint32_t bS = smem_u32(&Bs[0][0][0]);
    const uint32_t BUF = 128 * 80;           // bytes per buffer
    const uint32_t dA0 = lr * 80 + kc * 16;
    const uint32_t dA1 = (lr + 64) * 80 + kc * 16;

#define LOAD_TILE(buf, k0)                                   \
    do {                                                     \
        cp_async16(aS + (buf) * BUF + dA0, Ag0 + (k0));      \
        cp_async16(aS + (buf) * BUF + dA1, Ag1 + (k0));      \
        cp_async16(bS + (buf) * BUF + dA0, Bg0 + (k0));      \
        cp_async16(bS + (buf) * BUF + dA1, Bg1 + (k0));      \
        CP_COMMIT();                                         \
    } while (0)

    LOAD_TILE(0, 0);
    LOAD_TILE(1, 32);

    // fragment addresses (constant across tiles except buffer offset)
    const uint32_t aFrag = aS + (wm + (lane & 15)) * 80 + (lane >> 4) * 16;
    const uint32_t bFrag = bS + (wn + (lane & 7)) * 80 + ((lane >> 3) & 1) * 16;

    const int NT = K3 / 32;   // 96
    for (int s = 0; s < NT; s++) {
        const int buf = s & 1;
        CP_WAIT1();
        __syncthreads();

#pragma unroll
        for (int ks = 0; ks < 32; ks += 16) {
            uint32_t afr[4][4], bfr[4][2];
#pragma unroll
            for (int im = 0; im < 4; im++)
                ldsm_x4(afr[im], aFrag + buf * BUF + im * (16 * 80) + ks * 2);
#pragma unroll
            for (int in = 0; in < 4; in++)
                ldsm_x2(bfr[in], bFrag + buf * BUF + in * (8 * 80) + ks * 2);
#pragma unroll
            for (int im = 0; im < 4; im++)
#pragma unroll
                for (int in = 0; in < 4; in++)
                    mma16816(acc[im][in], afr[im], bfr[in]);
        }

        __syncthreads();
        if (s + 2 < NT) LOAD_TILE(buf, (s + 2) * 32);
    }
#undef LOAD_TILE

    // epilogue: each atom's frag = rows (er, er+8), cols (ec, ec+1)
    const int er = lane >> 2;
    const int ec = (lane & 3) * 2;
#pragma unroll
    for (int im = 0; im < 4; im++) {
#pragma unroll
        for (int in = 0; in < 4; in++) {
            const int row = bm + wm + im * 16 + er;
            const int col = bn + wn + in * 8 + ec;
            float2 c01 = make_float2(acc[im][in][0], acc[im][in][1]);
            float2 c23 = make_float2(acc[im][in][2], acc[im][in][3]);
            *(float2*)&C[(size_t)row * N + col]       = c01;
            *(float2*)&C[(size_t)(row + 8) * N + col] = c23;
        }
    }
}

// ---------------------------------------------------------------------------
// b/a projections + beta / alpha
// ---------------------------------------------------------------------------
__global__ void __launch_bounds__(256) smallproj_kernel(const float* __restrict__ hs,
                                                        const float* __restrict__ b_w,
                                                        const float* __restrict__ a_w,
                                                        const float* __restrict__ dt_bias,
                                                        const float* __restrict__ A_log) {
    __shared__ float sh[1024];
    const int bt  = blockIdx.x;
    const int tid = threadIdx.x;
    const float* row = hs + (size_t)bt * 1024;
    *(float4*)&sh[tid * 4] = *(const float4*)(row + tid * 4);
    __syncthreads();

    const int h = tid >> 5, lane = tid & 31;
    const float* bw = b_w + h * 1024;
    const float* aw = a_w + h * 1024;
    float sb = 0.f, sa = 0.f;
#pragma unroll
    for (int i = 0; i < 8; i++) {
        int idx = lane * 4 + i * 128;
        float4 x  = *(float4*)&sh[idx];
        float4 wb = *(const float4*)(bw + idx);
        float4 wa = *(const float4*)(aw + idx);
        sb += x.x * wb.x + x.y * wb.y + x.z * wb.z + x.w * wb.w;
        sa += x.x * wa.x + x.y * wa.y + x.z * wa.z + x.w * wa.w;
    }
#pragma unroll
    for (int m = 16; m; m >>= 1) {
        sb += __shfl_xor_sync(0xffffffffu, sb, m);
        sa += __shfl_xor_sync(0xffffffffu, sa, m);
    }
    if (lane == 0) {
        float beta = 1.f / (1.f + expf(-sb));
        float x  = sa + dt_bias[h];
        float sp = (x > 20.f) ? x : log1pf(expf(x));
        float g  = -expf(A_log[h]) * sp;
        int b = bt >> 10, t = bt & 1023;
        g_alpha[((b * NH + h) << 10) + t] = expf(g);
        g_beta [((b * NH + h) << 10) + t] = beta;
    }
}

// ---------------------------------------------------------------------------
// Causal depthwise conv1d (K=4)
// ---------------------------------------------------------------------------
__global__ void __launch_bounds__(256) conv_kernel(const float* __restrict__ conv_w) {
    const int c  = blockIdx.x * 256 + threadIdx.x;
    const int t0 = blockIdx.y * 128;
    const int b  = blockIdx.z;
    float4 w4 = *(const float4*)(conv_w + c * 4);
    const float* xin  = g_mixed + (size_t)b * TT * CDIM + c;
    float*       yout = g_qkvc  + (size_t)b * TT * CDIM + c;
    float x0 = (t0 >= 3) ? xin[(size_t)(t0 - 3) * CDIM] : 0.f;
    float x1 = (t0 >= 2) ? xin[(size_t)(t0 - 2) * CDIM] : 0.f;
    float x2 = (t0 >= 1) ? xin[(size_t)(t0 - 1) * CDIM] : 0.f;
#pragma unroll 4
    for (int t = t0; t < t0 + 128; t++) {
        float x3 = xin[(size_t)t * CDIM];
        yout[(size_t)t * CDIM] = w4.x * x0 + w4.y * x1 + w4.z * x2 + w4.w * x3;
        x0 = x1; x1 = x2; x2 = x3;
    }
}

// ---------------------------------------------------------------------------
// Gated delta-rule scan (R5 structure, scalar FFMA math).
// grid = (4 dv-chunks, H, B) = 128 CTAs, 256 threads.
// ---------------------------------------------------------------------------
__global__ void __launch_bounds__(256) scan_kernel() {
    __shared__ float sk[16][160];
    __shared__ float sq[16][160];
    __shared__ float sv[16][32];
    __shared__ float so[16][32];
    __shared__ float sal[16];
    __shared__ float sbe[16];

    const int tid   = threadIdx.x;
    const int chunk = blockIdx.x;
    const int h     = blockIdx.y;
    const int b     = blockIdx.z;

    const int lane  = tid & 31;
    const int w     = tid >> 5;
    const int split = lane & 7;
    const int col   = w * 4 + (lane >> 3);
    const int kbp   = split * 20;

    const float* qbase = g_qkvc + (size_t)b * TT * CDIM + h * 128;
    const float* abase = g_alpha + ((size_t)(b * NH + h) << 10);
    const float* bbase = g_beta  + ((size_t)(b * NH + h) << 10);

    float S[16];
#pragma unroll
    for (int j = 0; j < 16; j++) S[j] = 0.f;

    const int ltt  = tid >> 4;
    const int lseg = tid & 15;
    const int cc0  = lseg * 8;
    const int cc1  = cc0 + 4;
    const int d0   = cc0 + ((cc0 >> 4) << 2);
    const int d1   = cc1 + ((cc1 >> 4) << 2);

    float4 pq0, pq1, pk0, pk1, pv;
    float pal = 0.f, pbe = 0.f;
    {
        const float* row = qbase + (size_t)ltt * CDIM;
        pq0 = *(const float4*)(row + cc0);
        pq1 = *(const float4*)(row + cc1);
        pk0 = *(const float4*)(row + 1024 + cc0);
        pk1 = *(const float4*)(row + 1024 + cc1);
        if (lseg < 8) pv = *(const float4*)(row + 2048 + chunk * 32 + lseg * 4);
        if (tid < 16) { pal = abase[tid]; pbe = bbase[tid]; }
    }

    for (int t0 = 0; t0 < TT; t0 += 16) {
        __syncthreads();
        if (t0 > 0) {
            for (int idx = tid; idx < 512; idx += 256) {
                int tt = idx >> 5, dd = idx & 31;
                g_opre[(((size_t)(b * TT + (t0 - 16) + tt)) * NH + h) * 128 + chunk * 32 + dd] = so[tt][dd];
            }
        }
        *(float4*)&sq[ltt][d0] = pq0;
        *(float4*)&sq[ltt][d1] = pq1;
        *(float4*)&sk[ltt][d0] = pk0;
        *(float4*)&sk[ltt][d1] = pk1;
        if (lseg < 8) *(float4*)&sv[ltt][lseg * 4] = pv;
        if (tid < 16) { sal[tid] = pal; sbe[tid] = pbe; }
        __syncthreads();

        if (t0 + 16 < TT) {
            const float* row = qbase + (size_t)(t0 + 16 + ltt) * CDIM;
            pq0 = *(const float4*)(row + cc0);
            pq1 = *(const float4*)(row + cc1);
            pk0 = *(const float4*)(row + 1024 + cc0);
            pk1 = *(const float4*)(row + 1024 + cc1);
            if (lseg < 8) pv = *(const float4*)(row + 2048 + chunk * 32 + lseg * 4);
            if (tid < 16) { pal = abase[t0 + 16 + tid]; pbe = bbase[t0 + 16 + tid]; }
        }

#pragma unroll 2
        for (int tt = 0; tt < 16; tt++) {
            const float alpha = sal[tt];
            const float beta  = sbe[tt];

            float kr[16];
#pragma unroll
            for (int uu = 0; uu < 4; uu++)
                *(float4*)&kr[uu * 4] = *(float4*)&sk[tt][kbp + uu * 4];

            float kva = 0.f, kvb = 0.f, kvc = 0.f, kvd = 0.f;
#pragma unroll
            for (int j = 0; j < 16; j += 4) {
                S[j]     *= alpha; kva = fmaf(kr[j],     S[j],     kva);
                S[j + 1] *= alpha; kvb = fmaf(kr[j + 1], S[j + 1], kvb);
                S[j + 2] *= alpha; kvc = fmaf(kr[j + 2], S[j + 2], kvc);
                S[j + 3] *= alpha; kvd = fmaf(kr[j + 3], S[j + 3], kvd);
            }
            float kv = (kva + kvb) + (kvc + kvd);
            kv += __shfl_xor_sync(0xffffffffu, kv, 1);
            kv += __shfl_xor_sync(0xffffffffu, kv, 2);
            kv += __shfl_xor_sync(0xffffffffu, kv, 4);

            const float wv = (sv[tt][col] - kv) * beta;

            float qr[16];
#pragma unroll
            for (int uu = 0; uu < 4; uu++)
                *(float4*)&qr[uu * 4] = *(float4*)&sq[tt][kbp + uu * 4];

            float oa = 0.f, ob = 0.f, oc = 0.f, od = 0.f;
#pragma unroll
            for (int j = 0; j < 16; j += 4) {
                S[j]     = fmaf(kr[j],     wv, S[j]);     oa = fmaf(qr[j],     S[j],     oa);
                S[j + 1] = fmaf(kr[j + 1], wv, S[j + 1]); ob = fmaf(qr[j + 1], S[j + 1], ob);
                S[j + 2] = fmaf(kr[j + 2], wv, S[j + 2]); oc = fmaf(qr[j + 2], S[j + 2], oc);
                S[j + 3] = fmaf(kr[j + 3], wv, S[j + 3]); od = fmaf(qr[j + 3], S[j + 3], od);
            }
            float o = (oa + ob) + (oc + od);
            o += __shfl_xor_sync(0xffffffffu, o, 1);
            o += __shfl_xor_sync(0xffffffffu, o, 2);
            o += __shfl_xor_sync(0xffffffffu, o, 4);
            if (split == 0) so[tt][col] = o;
        }
    }

    __syncthreads();
    for (int idx = tid; idx < 512; idx += 256) {
        int tt = idx >> 5, dd = idx & 31;
        g_opre[(((size_t)(b * TT + (TT - 16) + tt)) * NH + h) * 128 + chunk * 32 + dd] = so[tt][dd];
    }
}

// ---------------------------------------------------------------------------
// Gated RMSNorm fused with split-bf16 A-operand emission for the out GEMM
// ---------------------------------------------------------------------------
__global__ void __launch_bounds__(256) normgate_kernel(const float* __restrict__ norm_w) {
    const int bt   = blockIdx.x;
    const int h    = threadIdx.x >> 5;
    const int lane = threadIdx.x & 31;

    const size_t obase = ((size_t)bt * NH + h) * 128 + lane * 4;
    float4 o4 = *(const float4*)(g_opre + obase);
    float ss = o4.x * o4.x + o4.y * o4.y + o4.z * o4.z + o4.w * o4.w;
#pragma unroll
    for (int m = 16; m; m >>= 1) ss += __shfl_xor_sync(0xffffffffu, ss, m);
    const float scale = rsqrtf(ss * (1.f / 128.f) + 1e-6f);

    const size_t zbase = (size_t)bt * 1024 + h * 128 + lane * 4;
    float4 z4 = *(const float4*)(g_z + zbase);
    float4 nw = *(const float4*)(norm_w + lane * 4);
    float rx = o4.x * scale * nw.x * (z4.x / (1.f + expf(-z4.x)));
    float ry = o4.y * scale * nw.y * (z4.y / (1.f + expf(-z4.y)));
    float rz = o4.z * scale * nw.z * (z4.z / (1.f + expf(-z4.z)));
    float rw = o4.w * scale * nw.w * (z4.w / (1.f + expf(-z4.w)));

    __nv_bfloat16 h0, h1, h2, h3, l0, l1, l2, l3;
    split_bf16(rx, h0, l0); split_bf16(ry, h1, l1);
    split_bf16(rz, h2, l2); split_bf16(rw, h3, l3);
    __nv_bfloat16* dst = g_A3og + (size_t)bt * K3 + h * 128 + lane * 4;
    st_bf16x4(dst,        h0, h1, h2, h3);
    st_bf16x4(dst + 1024, l0, l1, l2, l3);
    st_bf16x4(dst + 2048, h0, h1, h2, h3);
}

// ---------------------------------------------------------------------------
// kernel_launch
// ---------------------------------------------------------------------------
extern "C" void kernel_launch(void* const* d_in, const int* in_sizes, int n_in,
                              void* d_out, int out_size) {
    const float* hs      = (const float*)d_in[0];
    const float* qkv_w   = (const float*)d_in[1];
    const float* z_w     = (const float*)d_in[2];
    const float* b_w     = (const float*)d_in[3];
    const float* a_w     = (const float*)d_in[4];
    const float* conv_w  = (const float*)d_in[5];
    const float* dt_bias = (const float*)d_in[6];
    const float* A_log   = (const float*)d_in[7];
    const float* norm_w  = (const float*)d_in[8];
    const float* out_w   = (const float*)d_in[9];
    float* out = (float*)d_out;

    // operand conversions + alpha/beta (independent of each other)
    convert_hs_kernel<<<BB * TT, 256>>>(hs);
    convert_w_kernel<0><<<CDIM, 256>>>(qkv_w);
    convert_w_kernel<1><<<HIDN, 256>>>(z_w);
    convert_w_kernel<2><<<HIDN, 256>>>(out_w);
    smallproj_kernel<<<BB * TT, 256>>>(hs, b_w, a_w, dt_bias, A_log);

    // qkv projection (HMMA) -> g_mixed
    gemm_mma<0><<<dim3(CDIM / 128, (BB * TT) / 128), 256>>>(nullptr, CDIM);
    // causal depthwise conv -> g_qkvc
    conv_kernel<<<dim3(CDIM / 256, TT / 128, BB), 256>>>(conv_w);
    // z projection -> g_z
    gemm_mma<1><<<dim3(HIDN / 128, (BB * TT) / 128), 256>>>(nullptr, HIDN);
    // gated delta-rule recurrence -> g_opre
    scan_kernel<<<dim3(4, NH, BB), 256>>>();
    // gated RMSNorm + split-bf16 emission -> g_A3og
    normgate_kernel<<<BB * TT, 256>>>(norm_w);
    // output projection -> d_out
    gemm_mma<2><<<dim3(HIDN / 128, (BB * TT) / 128), 256>>>(out, HIDN);
}